// round 16
// baseline (speedup 1.0000x reference)
#include <cuda_runtime.h>
#include <math.h>

__device__ float g_feats[4096 * 64];
__device__ float g_lors[512 * 24 * 64];
__device__ float g_U[2 * 16 * 32 * 32];
__device__ float g_tagw[4 * 64];
__device__ float g_ploss[128];
__device__ float g_pcorr[128];

__device__ __forceinline__ float gelu_f(float x) {
    return 0.5f * x * (1.0f + erff(x * 0.70710678118654752f));
}

__global__ void prep_kernel(const float* __restrict__ w1, const float* __restrict__ tags)
{
    int id = threadIdx.x;
    int tg = id >> 6;
    int e = id & 63;
    float s = 0.f;
    for (int d = 0; d < 64; d++) s = fmaf(w1[e * 64 + d], tags[tg * 64 + d], s);
    g_tagw[tg * 64 + e] = s;
}

__global__ void wtrans_kernel(const float* __restrict__ c2w, const float* __restrict__ c3w)
{
    int L = blockIdx.x;
    const float* wsrc = L ? c3w : c2w;
    for (int id = threadIdx.x; id < 1024; id += 256) {
        int ci = id & 31;
        int co = id >> 5;
        int slot = (co & 7) * 4 + (co >> 3);
        const float* g = wsrc + (co * 32 + ci) * 9;
        float tr[4][3];
        for (int j = 0; j < 3; j++) {
            float g0 = g[j], g1 = g[3 + j], g2 = g[6 + j];
            tr[0][j] = g0;
            tr[1][j] = 0.5f * (g0 + g1 + g2);
            tr[2][j] = 0.5f * (g0 - g1 + g2);
            tr[3][j] = g2;
        }
        for (int i = 0; i < 4; i++) {
            float t0 = tr[i][0], t1 = tr[i][1], t2 = tr[i][2];
            float u0 = t0;
            float u1 = 0.5f * (t0 + t1 + t2);
            float u2 = 0.5f * (t0 - t1 + t2);
            float u3 = t2;
            int base = ((L * 16 + i * 4) * 32 + ci) * 32 + slot;
            g_U[base]            = u0;
            g_U[base + 1 * 1024] = u1;
            g_U[base + 2 * 1024] = u2;
            g_U[base + 3 * 1024] = u3;
        }
    }
}

// ============ feature extractor: 1 image/block, 512 threads ============
__global__ __launch_bounds__(512, 2) void feat_kernel(
    const float* __restrict__ sxs, const float* __restrict__ qxs,
    const float* __restrict__ c1w, const float* __restrict__ c1b, const float* __restrict__ bn1,
    const float* __restrict__ c2b, const float* __restrict__ bn2,
    const float* __restrict__ c3b, const float* __restrict__ bn3,
    const float* __restrict__ c4w, const float* __restrict__ c4b, const float* __restrict__ bn4,
    const float* __restrict__ lin_w)
{
    extern __shared__ float sm[];
    float* Vs   = sm;
    float* bufA = sm + 8192;
    float* bufB = sm + 11492;
    float* w1s  = sm + 14792;
    float* w4s  = sm + 15080;
    float* A1 = sm + 15368; float* B1 = sm + 15400;
    float* A2 = sm + 15432; float* B2 = sm + 15464;
    float* A3 = sm + 15496; float* B3 = sm + 15528;
    float* AB4 = sm + 15560;
    float* flat = sm + 15568;
    float* red = sm + 15632;
    float* Ms = sm + 16144;

    const int t = threadIdx.x;
    const int c = t & 31;
    const int g16 = t >> 5;
    const int img = blockIdx.x;
    const float* src = (img < 3072) ? (sxs + img * 784) : (qxs + (img - 3072) * 784);

    for (int i = t; i < 288; i += 512) {
        int co = i / 9; int k = i - co * 9;
        w1s[k * 32 + co] = c1w[i];
        w4s[i] = c4w[i];
    }
    if (t < 32) {
        float g = bn1[t], bt = bn1[32 + t], m = bn1[64 + t], v = bn1[96 + t];
        float sc = g * rsqrtf(v + 1e-5f);
        A1[t] = sc * 0.0625f;
        B1[t] = (c1b[t] - m) * sc + bt;
        g = bn2[t]; bt = bn2[32 + t]; m = bn2[64 + t]; v = bn2[96 + t];
        sc = g * rsqrtf(v + 1e-5f);
        A2[t] = sc; B2[t] = (c2b[t] - m) * sc + bt;
        g = bn3[t]; bt = bn3[32 + t]; m = bn3[64 + t]; v = bn3[96 + t];
        sc = g * rsqrtf(v + 1e-5f);
        A3[t] = sc; B3[t] = (c3b[t] - m) * sc + bt;
    }
    if (t == 0) {
        float g = bn4[0], bt = bn4[1], m = bn4[2], v = bn4[3];
        float sc = g * rsqrtf(v + 1e-5f);
        AB4[0] = sc; AB4[1] = (c4b[0] - m) * sc + bt;
    }
    for (int i = t; i < 3300; i += 512) { bufA[i] = 0.f; bufB[i] = 0.f; }

    float* inpad = Vs;
    float* rs4 = Vs + 1024;
    float* Ws = Vs + 2048;
    for (int i = t; i < 900; i += 512) {
        int yy = i / 30; int xx = i - yy * 30;
        float v = 0.f;
        if (yy >= 1 && yy <= 28 && xx >= 1 && xx <= 28) v = src[(yy - 1) * 28 + xx - 1];
        inpad[i] = v;
    }
    __syncthreads();
    {
        const int SO[8] = {0, 3, 7, 10, 14, 17, 21, 24};
        for (int i = t; i < 720; i += 512) {
            int u = i / 24; int b3 = i - u * 24;
            int b = SO[b3 / 3] + (b3 % 3);
            const float* ip = inpad + u * 30 + b;
            rs4[i] = ip[0] + ip[1] + ip[2] + ip[3];
        }
        __syncthreads();
        for (int i = t; i < 576; i += 512) {
            int a3 = i / 24; int b3 = i - a3 * 24;
            int a = SO[a3 / 3] + (a3 % 3);
            Ws[i] = rs4[a * 24 + b3] + rs4[(a + 1) * 24 + b3] + rs4[(a + 2) * 24 + b3] + rs4[(a + 3) * 24 + b3];
        }
        __syncthreads();
        int y = g16 >> 1;
        int x0 = (g16 & 1) * 4;
        float acc[4];
        for (int x = 0; x < 4; x++) acc[x] = 0.f;
        for (int dy = 0; dy < 3; dy++) for (int dx = 0; dx < 3; dx++) {
            float wv = w1s[(dy * 3 + dx) * 32 + c];
            for (int x = 0; x < 4; x++) acc[x] = fmaf(wv, Ws[(3 * y + dy) * 24 + 3 * (x0 + x) + dx], acc[x]);
        }
        float a1 = A1[c], b1 = B1[c];
        for (int x = 0; x < 4; x++) bufA[((y + 1) * 10 + x0 + x + 1) * 33 + c] = gelu_f(acc[x] * a1 + b1);
    }
    __syncthreads();

    for (int L = 0; L < 2; L++) {
        const float* inb = L ? bufB : bufA;
        float* outb = L ? bufA : bufB;
        const float* Asc = L ? A3 : A2;
        const float* Bof = L ? B3 : B2;

        {
            int tl = t & 15; int ci = t >> 4;
            int ty = tl >> 2; int tx = tl & 3;
            const float* base = inb + (2 * ty * 10 + 2 * tx) * 33 + ci;
            float d[4][4];
            for (int r = 0; r < 4; r++) for (int cc = 0; cc < 4; cc++) d[r][cc] = base[(r * 10 + cc) * 33];
            float tm[4][4];
            for (int j = 0; j < 4; j++) {
                tm[0][j] = d[0][j] - d[2][j];
                tm[1][j] = d[1][j] + d[2][j];
                tm[2][j] = d[2][j] - d[1][j];
                tm[3][j] = d[1][j] - d[3][j];
            }
            for (int i = 0; i < 4; i++) {
                Vs[(i * 4 + 0) * 512 + ci * 16 + tl] = tm[i][0] - tm[i][2];
                Vs[(i * 4 + 1) * 512 + ci * 16 + tl] = tm[i][1] + tm[i][2];
                Vs[(i * 4 + 2) * 512 + ci * 16 + tl] = tm[i][2] - tm[i][1];
                Vs[(i * 4 + 3) * 512 + ci * 16 + tl] = tm[i][1] - tm[i][3];
            }
        }
        __syncthreads();

        {
            int uv = g16;
            int q = c >> 3;
            int j = c & 7;
            float acc[16];
            for (int i = 0; i < 16; i++) acc[i] = 0.f;
            const float4* V4 = (const float4*)(Vs + uv * 512) + q;
            const float4* U4 = (const float4*)(g_U + (L * 16 + uv) * 1024) + j;
            #pragma unroll 8
            for (int ci = 0; ci < 32; ci++) {
                float4 v = V4[ci * 4];
                float4 u = U4[ci * 8];
                acc[0]  = fmaf(v.x, u.x, acc[0]);
                acc[1]  = fmaf(v.x, u.y, acc[1]);
                acc[2]  = fmaf(v.x, u.z, acc[2]);
                acc[3]  = fmaf(v.x, u.w, acc[3]);
                acc[4]  = fmaf(v.y, u.x, acc[4]);
                acc[5]  = fmaf(v.y, u.y, acc[5]);
                acc[6]  = fmaf(v.y, u.z, acc[6]);
                acc[7]  = fmaf(v.y, u.w, acc[7]);
                acc[8]  = fmaf(v.z, u.x, acc[8]);
                acc[9]  = fmaf(v.z, u.y, acc[9]);
                acc[10] = fmaf(v.z, u.z, acc[10]);
                acc[11] = fmaf(v.z, u.w, acc[11]);
                acc[12] = fmaf(v.w, u.x, acc[12]);
                acc[13] = fmaf(v.w, u.y, acc[13]);
                acc[14] = fmaf(v.w, u.z, acc[14]);
                acc[15] = fmaf(v.w, u.w, acc[15]);
            }
            float* Mw = Ms + uv * 544 + (q * 4) * 34 + j;
            for (int tlk = 0; tlk < 4; tlk++)
                for (int k = 0; k < 4; k++)
                    Mw[tlk * 34 + k * 8] = acc[tlk * 4 + k];
        }
        __syncthreads();

        {
            int co2 = t & 31; int tl = t >> 5;
            int ty = tl >> 2; int tx = tl & 3;
            float M[4][4];
            for (int i = 0; i < 4; i++) for (int j = 0; j < 4; j++) M[i][j] = Ms[(i * 4 + j) * 544 + tl * 34 + co2];
            float t0[2][4];
            for (int j = 0; j < 4; j++) {
                t0[0][j] = M[0][j] + M[1][j] + M[2][j];
                t0[1][j] = M[1][j] - M[2][j] - M[3][j];
            }
            float a = Asc[co2], bo = Bof[co2];
            for (int i = 0; i < 2; i++) {
                float y0 = t0[i][0] + t0[i][1] + t0[i][2];
                float y1 = t0[i][1] - t0[i][2] - t0[i][3];
                int rr = 1 + 2 * ty + i;
                int cc0 = 1 + 2 * tx;
                outb[(rr * 10 + cc0) * 33 + co2] = gelu_f(y0 * a + bo);
                outb[(rr * 10 + cc0 + 1) * 33 + co2] = gelu_f(y1 * a + bo);
            }
        }
        __syncthreads();
    }

    {
        int y = g16 >> 1;
        int x0 = (g16 & 1) * 4;
        float acc[4];
        for (int x = 0; x < 4; x++) acc[x] = 0.f;
        for (int dy = 0; dy < 3; dy++) for (int dx = 0; dx < 3; dx++) {
            float wv = w4s[c * 9 + dy * 3 + dx];
            const float* rp = bufA + ((y + dy) * 10 + x0 + dx) * 33 + c;
            for (int x = 0; x < 4; x++) acc[x] = fmaf(wv, rp[x * 33], acc[x]);
        }
        for (int x = 0; x < 4; x++) {
            float v = acc[x];
            for (int o = 16; o; o >>= 1) v += __shfl_xor_sync(0xffffffffu, v, o);
            if (c == 0) flat[y * 8 + x0 + x] = gelu_f(v * AB4[0] + AB4[1]);
        }
    }
    __syncthreads();

    {
        int e = t & 63;
        int h = t >> 6;
        int j0 = h * 8;
        float p = 0.f;
        for (int jj = 0; jj < 8; jj += 4) {
            float4 lw = *(const float4*)(lin_w + e * 64 + j0 + jj);
            p = fmaf(lw.x, flat[j0 + jj], p);
            p = fmaf(lw.y, flat[j0 + jj + 1], p);
            p = fmaf(lw.z, flat[j0 + jj + 2], p);
            p = fmaf(lw.w, flat[j0 + jj + 3], p);
        }
        red[h * 64 + e] = p;
        __syncthreads();
        if (t < 64) {
            float s = 0.f;
            for (int h2 = 0; h2 < 8; h2++) s += red[h2 * 64 + t];
            g_feats[img * 64 + t] = s;
        }
    }
}

// ============ LoR adapter: 16 tokens/block x 64 threads, float4 GEMVs ============
__global__ __launch_bounds__(1024) void lor_kernel(
    const float* __restrict__ emb, const float* __restrict__ w1, const float* __restrict__ w2,
    const float* __restrict__ tags, const float* __restrict__ rq, const float* __restrict__ rk,
    const float* __restrict__ rv, const float* __restrict__ ro,
    const float* __restrict__ lnw, const float* __restrict__ lnb, const int* __restrict__ sys)
{
    extern __shared__ float sm[];
    float* w1S = sm;             // 4352 = 64 x stride68, row e, natural [e][d]
    float* w2S = sm + 4352;      // 4352
    float* rqS = sm + 8704;      // 4352
    float* roS = sm + 13056;     // 4352 (transposed to [j][d])
    float* rkT = sm + 17408;     // 1024
    float* rvS = sm + 18432;     // 1024
    float* partS = sm + 19456;   // 1024
    float* ahs = sm + 20480;     // 1024
    float* qvs = sm + 21504;     // 1024
    float* lvs = sm + 22528;     // 1024
    float* rA = sm + 23552;      // 32
    float* rB = sm + 23584;      // 32
    float* bndS = sm + 23616;    // 256
    float* tgS = sm + 23872;     // 256
    float* tgwS = sm + 24128;    // 256 -> total 24384 floats
    const int t = threadIdx.x;

    for (int i = t; i < 4096; i += 1024) {
        int e = i >> 6; int d = i & 63;
        w1S[e * 68 + d] = w1[i];
        w2S[e * 68 + d] = w2[i];
        rqS[e * 68 + d] = rq[i];
    }
    {
        int n = t >> 8; int h = (t >> 4) & 15; int r = t & 15;
        rkT[t] = rk[(r * 4 + n) * 16 + h];
        rvS[t] = rv[t];
    }
    if (t < 256) {
        tgS[t] = tags[t];
        tgwS[t] = g_tagw[t];
    }
    // transpose ro [d][j] -> roS [j][d] via partS chunks
    for (int c4 = 0; c4 < 4; c4++) {
        __syncthreads();
        partS[t] = ro[c4 * 1024 + t];
        __syncthreads();
        int jj = t & 63; int dd = t >> 6;   // dd 0..15
        roS[jj * 68 + c4 * 16 + dd] = partS[dd * 64 + jj];
    }

    const int lt = t >> 6;
    const int j = t & 63;
    const int tok = blockIdx.x * 16 + lt;
    const int b = tok / 24;
    const int k24 = tok - b * 24;
    const int s = k24 >> 2;
    const int tg = k24 & 3;
    const int g4 = lt >> 2;
    if ((lt & 3) == 0) {
        int cls = sys[b * 6 + s];
        bndS[g4 * 64 + j] = g_feats[(b * 6 + s) * 64 + j] + emb[cls * 64 + j];
    }
    __syncthreads();
    // first GEMV: thread (lt = g4*4+p, j) does d in [p*16, p*16+16), float4
    {
        int p = lt & 3;
        float hp = 0.f;
        const float4* wr = (const float4*)(w1S + j * 68) + p * 4;
        const float4* ar = (const float4*)(bndS + g4 * 64) + p * 4;
        #pragma unroll
        for (int k = 0; k < 4; k++) {
            float4 w = wr[k];
            float4 a = ar[k];
            hp = fmaf(w.x, a.x, hp);
            hp = fmaf(w.y, a.y, hp);
            hp = fmaf(w.z, a.z, hp);
            hp = fmaf(w.w, a.w, hp);
        }
        partS[t] = hp;
    }
    __syncthreads();
    float h1 = partS[(g4 * 4 + 0) * 64 + j] + partS[(g4 * 4 + 1) * 64 + j]
             + partS[(g4 * 4 + 2) * 64 + j] + partS[(g4 * 4 + 3) * 64 + j]
             + tgwS[tg * 64 + j];
    ahs[t] = gelu_f(h1);
    __syncthreads();
    float qv = 0.f;
    {
        const float4* wr = (const float4*)(w2S + j * 68);
        const float4* ar = (const float4*)(ahs + lt * 64);
        #pragma unroll
        for (int k = 0; k < 16; k++) {
            float4 w = wr[k];
            float4 a = ar[k];
            qv = fmaf(w.x, a.x, qv);
            qv = fmaf(w.y, a.y, qv);
            qv = fmaf(w.z, a.z, qv);
            qv = fmaf(w.w, a.w, qv);
        }
    }
    qvs[t] = qv;
    __syncthreads();
    float qh = 0.f;
    {
        const float4* wr = (const float4*)(rqS + j * 68);
        const float4* ar = (const float4*)(qvs + lt * 64);
        #pragma unroll
        for (int k = 0; k < 16; k++) {
            float4 w = wr[k];
            float4 a = ar[k];
            qh = fmaf(w.x, a.x, qh);
            qh = fmaf(w.y, a.y, qh);
            qh = fmaf(w.z, a.z, qh);
            qh = fmaf(w.w, a.w, qh);
        }
    }
    const int n = j >> 4;
    const int sub = j & 15;
    float scv = 0.f;
    for (int hh = 0; hh < 16; hh++) {
        float q2 = __shfl_sync(0xffffffffu, qh, hh, 16);
        scv = fmaf(q2, rkT[(n * 16 + hh) * 16 + sub], scv);
    }
    scv *= 0.25f;
    float mx = scv;
    for (int o = 8; o; o >>= 1) mx = fmaxf(mx, __shfl_xor_sync(0xffffffffu, mx, o, 16));
    float ee = expf(scv - mx);
    float ss = ee;
    for (int o = 8; o; o >>= 1) ss += __shfl_xor_sync(0xffffffffu, ss, o, 16);
    float p = ee / ss;
    float lv = 0.f;
    for (int r = 0; r < 16; r++) {
        float pr = __shfl_sync(0xffffffffu, p, r, 16);
        lv = fmaf(pr, rvS[(r * 4 + n) * 16 + sub], lv);
    }
    lvs[t] = lv;
    __syncthreads();
    float ov = 0.f;
    {
        const float4* wr = (const float4*)(roS + j * 68);
        const float4* ar = (const float4*)(lvs + lt * 64);
        #pragma unroll
        for (int k = 0; k < 16; k++) {
            float4 w = wr[k];
            float4 a = ar[k];
            ov = fmaf(w.x, a.x, ov);
            ov = fmaf(w.y, a.y, ov);
            ov = fmaf(w.z, a.z, ov);
            ov = fmaf(w.w, a.w, ov);
        }
    }
    float z = ov + bndS[g4 * 64 + j] + tgS[tg * 64 + j];
    float sv = z;
    for (int o = 16; o; o >>= 1) sv += __shfl_xor_sync(0xffffffffu, sv, o);
    int wh = j >> 5;
    if ((j & 31) == 0) rA[lt * 2 + wh] = sv;
    __syncthreads();
    float mean = (rA[lt * 2] + rA[lt * 2 + 1]) * 0.015625f;
    float dz = z - mean;
    float v2 = dz * dz;
    for (int o = 16; o; o >>= 1) v2 += __shfl_xor_sync(0xffffffffu, v2, o);
    if ((j & 31) == 0) rB[lt * 2 + wh] = v2;
    __syncthreads();
    float var = (rB[lt * 2] + rB[lt * 2 + 1]) * 0.015625f;
    g_lors[tok * 64 + j] = dz * rsqrtf(var + 1e-5f) * lnw[j] + lnb[j];
}

// ============ query path: 4 tasks/block, 256 threads, grid 128 ============
__global__ __launch_bounds__(256) void query_kernel(
    const float* __restrict__ emb, const float* __restrict__ w1, const float* __restrict__ w2,
    const float* __restrict__ tags, const int* __restrict__ qys)
{
    extern __shared__ float sm[];
    float* w1T = sm;
    float* w2T = sm + 4160;
    float* lorS = sm + 8320;
    float* xq = sm + 14464;
    float* ah = sm + 14976;
    float* pd = sm + 15488;
    float* d1 = sm + 16000;
    float* d2 = sm + 16048;
    float* lg = sm + 16096;
    float* ls = sm + 16112;
    float* cr = sm + 16120;
    const int t = threadIdx.x;
    for (int i = t; i < 4096; i += 256) {
        int e = i >> 6; int d = i & 63;
        w1T[d * 65 + e] = w1[i];
        w2T[d * 65 + e] = w2[i];
    }
    for (int i = t; i < 6144; i += 256) lorS[i] = g_lors[blockIdx.x * 6144 + i];
    const int bl = t >> 6;
    const int e = t & 63;
    const int b = blockIdx.x * 4 + bl;
    for (int q = 0; q < 2; q++) xq[(bl * 2 + q) * 64 + e] = g_feats[3072 * 64 + (b * 2 + q) * 64 + e] + tags[4 * 64 + e];
    __syncthreads();
    if (e < 12) {
        int s = e >> 1; int q = e & 1;
        const float* r1 = lorS + bl * 1536 + (s * 4 + 1) * 64;
        const float* xx = xq + (bl * 2 + q) * 64;
        float a = 0.f;
        for (int d = 0; d < 64; d++) a = fmaf(r1[d], xx[d], a);
        d1[bl * 12 + e] = a;
    }
    __syncthreads();
    for (int q = 0; q < 2; q++) {
        const float* xx = xq + (bl * 2 + q) * 64;
        float a = 0.f;
        for (int d = 0; d < 64; d++) a = fmaf(w1T[d * 65 + e], xx[d], a);
        for (int s = 0; s < 6; s++) a = fmaf(lorS[bl * 1536 + (s * 4) * 64 + e], d1[bl * 12 + s * 2 + q], a);
        ah[(bl * 2 + q) * 64 + e] = gelu_f(a);
    }
    __syncthreads();
    if (e < 12) {
        int s = e >> 1; int q = e & 1;
        const float* r2 = lorS + bl * 1536 + (s * 4 + 3) * 64;
        const float* aa = ah + (bl * 2 + q) * 64;
        float a = 0.f;
        for (int d = 0; d < 64; d++) a = fmaf(r2[d], aa[d], a);
        d2[bl * 12 + e] = a;
    }
    __syncthreads();
    for (int q = 0; q < 2; q++) {
        const float* aa = ah + (bl * 2 + q) * 64;
        float a = 0.f;
        for (int d = 0; d < 64; d++) a = fmaf(w2T[d * 65 + e], aa[d], a);
        for (int s = 0; s < 6; s++) a = fmaf(lorS[bl * 1536 + (s * 4 + 2) * 64 + e], d2[bl * 12 + s * 2 + q], a);
        pd[(bl * 2 + q) * 64 + e] = a;
    }
    __syncthreads();
    if (e < 4) {
        int q = e >> 1; int l = e & 1;
        float a = 0.f;
        for (int d = 0; d < 64; d++) a = fmaf(emb[l * 64 + d], pd[(bl * 2 + q) * 64 + d], a);
        lg[bl * 4 + e] = a;
    }
    __syncthreads();
    if (e < 2) {
        float l0 = lg[bl * 4 + e * 2];
        float l1 = lg[bl * 4 + e * 2 + 1];
        int yv = qys[b * 2 + e];
        float m = fmaxf(l0, l1);
        float lse = m + logf(expf(l0 - m) + expf(l1 - m));
        ls[bl * 2 + e] = lse - (yv ? l1 : l0);
        cr[bl * 2 + e] = (((l1 > l0) ? 1 : 0) == yv) ? 1.f : 0.f;
    }
    __syncthreads();
    if (t == 0) {
        float sl = 0.f;
        float sc = 0.f;
        for (int i = 0; i < 8; i++) { sl += ls[i]; sc += cr[i]; }
        g_ploss[blockIdx.x] = sl;
        g_pcorr[blockIdx.x] = sc;
    }
}

__global__ void reduce_kernel(float* __restrict__ out)
{
    __shared__ float sl[128];
    __shared__ float sc[128];
    int t = threadIdx.x;
    sl[t] = g_ploss[t];
    sc[t] = g_pcorr[t];
    __syncthreads();
    for (int s = 64; s; s >>= 1) {
        if (t < s) { sl[t] += sl[t + s]; sc[t] += sc[t + s]; }
        __syncthreads();
    }
    if (t == 0) {
        float loss = sl[0] * 0.0009765625f;
        out[0] = loss;
        out[1] = loss;
        out[2] = 0.f;
        out[3] = sc[0];
        out[4] = 1024.f;
    }
}

extern "C" void kernel_launch(void* const* d_in, const int* in_sizes, int n_in,
                              void* d_out, int out_size)
{
    const float* sxs = (const float*)d_in[1];
    const float* qxs = (const float*)d_in[2];
    const float* c1w = (const float*)d_in[4];
    const float* c1b = (const float*)d_in[5];
    const float* bn1 = (const float*)d_in[6];
    const float* c2w = (const float*)d_in[7];
    const float* c2b = (const float*)d_in[8];
    const float* bn2 = (const float*)d_in[9];
    const float* c3w = (const float*)d_in[10];
    const float* c3b = (const float*)d_in[11];
    const float* bn3 = (const float*)d_in[12];
    const float* c4w = (const float*)d_in[13];
    const float* c4b = (const float*)d_in[14];
    const float* bn4 = (const float*)d_in[15];
    const float* lin_w = (const float*)d_in[16];
    const float* emb = (const float*)d_in[17];
    const float* w1 = (const float*)d_in[18];
    const float* w2 = (const float*)d_in[19];
    const float* tags = (const float*)d_in[20];
    const float* rq = (const float*)d_in[21];
    const float* rk = (const float*)d_in[22];
    const float* rv = (const float*)d_in[23];
    const float* ro = (const float*)d_in[24];
    const float* lnw = (const float*)d_in[25];
    const float* lnb = (const float*)d_in[26];
    const int* sys = (const int*)d_in[27];
    const int* qys = (const int*)d_in[28];
    const size_t smF = 24848 * sizeof(float);
    const size_t smL = 24384 * sizeof(float);
    const size_t smQ = 16128 * sizeof(float);
    cudaFuncSetAttribute(feat_kernel, cudaFuncAttributeMaxDynamicSharedMemorySize, (int)smF);
    cudaFuncSetAttribute(lor_kernel, cudaFuncAttributeMaxDynamicSharedMemorySize, (int)smL);
    cudaFuncSetAttribute(query_kernel, cudaFuncAttributeMaxDynamicSharedMemorySize, (int)smQ);
    // lor_kernel sits at 0-based position 3 (ncu capture slot)
    wtrans_kernel<<<2, 256>>>(c2w, c3w);
    prep_kernel<<<1, 256>>>(w1, tags);
    feat_kernel<<<4096, 512, smF>>>(sxs, qxs, c1w, c1b, bn1, c2b, bn2, c3b, bn3, c4w, c4b, bn4, lin_w);
    lor_kernel<<<768, 1024, smL>>>(emb, w1, w2, tags, rq, rk, rv, ro, lnw, lnb, sys);
    query_kernel<<<128, 256, smQ>>>(emb, w1, w2, tags, qys);
    reduce_kernel<<<1, 128>>>((float*)d_out);
}

// round 17
// speedup vs baseline: 1.0304x; 1.0304x over previous
#include <cuda_runtime.h>
#include <math.h>

__device__ float g_feats[4096 * 64];
__device__ float g_lors[512 * 24 * 64];
__device__ float g_U[2 * 16 * 32 * 32];
__device__ float g_tagw[4 * 64];
__device__ float g_ploss[128];
__device__ float g_pcorr[128];

__device__ __forceinline__ float gelu_f(float x) {
    return 0.5f * x * (1.0f + erff(x * 0.70710678118654752f));
}

__global__ void prep_kernel(const float* __restrict__ w1, const float* __restrict__ tags)
{
    int id = threadIdx.x;
    int tg = id >> 6;
    int e = id & 63;
    float s = 0.f;
    for (int d = 0; d < 64; d++) s = fmaf(w1[e * 64 + d], tags[tg * 64 + d], s);
    g_tagw[tg * 64 + e] = s;
}

__global__ void wtrans_kernel(const float* __restrict__ c2w, const float* __restrict__ c3w)
{
    int L = blockIdx.x;
    const float* wsrc = L ? c3w : c2w;
    for (int id = threadIdx.x; id < 1024; id += 256) {
        int ci = id & 31;
        int co = id >> 5;
        int slot = (co & 7) * 4 + (co >> 3);
        const float* g = wsrc + (co * 32 + ci) * 9;
        float tr[4][3];
        for (int j = 0; j < 3; j++) {
            float g0 = g[j], g1 = g[3 + j], g2 = g[6 + j];
            tr[0][j] = g0;
            tr[1][j] = 0.5f * (g0 + g1 + g2);
            tr[2][j] = 0.5f * (g0 - g1 + g2);
            tr[3][j] = g2;
        }
        for (int i = 0; i < 4; i++) {
            float t0 = tr[i][0], t1 = tr[i][1], t2 = tr[i][2];
            float u0 = t0;
            float u1 = 0.5f * (t0 + t1 + t2);
            float u2 = 0.5f * (t0 - t1 + t2);
            float u3 = t2;
            int base = ((L * 16 + i * 4) * 32 + ci) * 32 + slot;
            g_U[base]            = u0;
            g_U[base + 1 * 1024] = u1;
            g_U[base + 2 * 1024] = u2;
            g_U[base + 3 * 1024] = u3;
        }
    }
}

// ============ feature extractor: 1 image/block, 512 threads ============
__global__ __launch_bounds__(512, 2) void feat_kernel(
    const float* __restrict__ sxs, const float* __restrict__ qxs,
    const float* __restrict__ c1w, const float* __restrict__ c1b, const float* __restrict__ bn1,
    const float* __restrict__ c2b, const float* __restrict__ bn2,
    const float* __restrict__ c3b, const float* __restrict__ bn3,
    const float* __restrict__ c4w, const float* __restrict__ c4b, const float* __restrict__ bn4,
    const float* __restrict__ lin_w)
{
    extern __shared__ float sm[];
    float* Vs   = sm;
    float* bufA = sm + 8192;
    float* bufB = sm + 11492;
    float* w1s  = sm + 14792;
    float* w4s  = sm + 15080;
    float* A1 = sm + 15368; float* B1 = sm + 15400;
    float* A2 = sm + 15432; float* B2 = sm + 15464;
    float* A3 = sm + 15496; float* B3 = sm + 15528;
    float* AB4 = sm + 15560;
    float* flat = sm + 15568;
    float* red = sm + 15632;
    float* Ms = sm + 16144;

    const int t = threadIdx.x;
    const int c = t & 31;
    const int g16 = t >> 5;
    const int img = blockIdx.x;
    const float* src = (img < 3072) ? (sxs + img * 784) : (qxs + (img - 3072) * 784);

    for (int i = t; i < 288; i += 512) {
        int co = i / 9; int k = i - co * 9;
        w1s[k * 32 + co] = c1w[i];
        w4s[i] = c4w[i];
    }
    if (t < 32) {
        float g = bn1[t], bt = bn1[32 + t], m = bn1[64 + t], v = bn1[96 + t];
        float sc = g * rsqrtf(v + 1e-5f);
        A1[t] = sc * 0.0625f;
        B1[t] = (c1b[t] - m) * sc + bt;
        g = bn2[t]; bt = bn2[32 + t]; m = bn2[64 + t]; v = bn2[96 + t];
        sc = g * rsqrtf(v + 1e-5f);
        A2[t] = sc; B2[t] = (c2b[t] - m) * sc + bt;
        g = bn3[t]; bt = bn3[32 + t]; m = bn3[64 + t]; v = bn3[96 + t];
        sc = g * rsqrtf(v + 1e-5f);
        A3[t] = sc; B3[t] = (c3b[t] - m) * sc + bt;
    }
    if (t == 0) {
        float g = bn4[0], bt = bn4[1], m = bn4[2], v = bn4[3];
        float sc = g * rsqrtf(v + 1e-5f);
        AB4[0] = sc; AB4[1] = (c4b[0] - m) * sc + bt;
    }
    for (int i = t; i < 3300; i += 512) { bufA[i] = 0.f; bufB[i] = 0.f; }

    float* inpad = Vs;
    float* rs4 = Vs + 1024;
    float* Ws = Vs + 2048;
    for (int i = t; i < 900; i += 512) {
        int yy = i / 30; int xx = i - yy * 30;
        float v = 0.f;
        if (yy >= 1 && yy <= 28 && xx >= 1 && xx <= 28) v = src[(yy - 1) * 28 + xx - 1];
        inpad[i] = v;
    }
    __syncthreads();
    {
        const int SO[8] = {0, 3, 7, 10, 14, 17, 21, 24};
        for (int i = t; i < 720; i += 512) {
            int u = i / 24; int b3 = i - u * 24;
            int b = SO[b3 / 3] + (b3 % 3);
            const float* ip = inpad + u * 30 + b;
            rs4[i] = ip[0] + ip[1] + ip[2] + ip[3];
        }
        __syncthreads();
        for (int i = t; i < 576; i += 512) {
            int a3 = i / 24; int b3 = i - a3 * 24;
            int a = SO[a3 / 3] + (a3 % 3);
            Ws[i] = rs4[a * 24 + b3] + rs4[(a + 1) * 24 + b3] + rs4[(a + 2) * 24 + b3] + rs4[(a + 3) * 24 + b3];
        }
        __syncthreads();
        int y = g16 >> 1;
        int x0 = (g16 & 1) * 4;
        float acc[4];
        for (int x = 0; x < 4; x++) acc[x] = 0.f;
        for (int dy = 0; dy < 3; dy++) for (int dx = 0; dx < 3; dx++) {
            float wv = w1s[(dy * 3 + dx) * 32 + c];
            for (int x = 0; x < 4; x++) acc[x] = fmaf(wv, Ws[(3 * y + dy) * 24 + 3 * (x0 + x) + dx], acc[x]);
        }
        float a1 = A1[c], b1 = B1[c];
        for (int x = 0; x < 4; x++) bufA[((y + 1) * 10 + x0 + x + 1) * 33 + c] = gelu_f(acc[x] * a1 + b1);
    }
    __syncthreads();

    for (int L = 0; L < 2; L++) {
        const float* inb = L ? bufB : bufA;
        float* outb = L ? bufA : bufB;
        const float* Asc = L ? A3 : A2;
        const float* Bof = L ? B3 : B2;

        {
            int tl = t & 15; int ci = t >> 4;
            int ty = tl >> 2; int tx = tl & 3;
            const float* base = inb + (2 * ty * 10 + 2 * tx) * 33 + ci;
            float d[4][4];
            for (int r = 0; r < 4; r++) for (int cc = 0; cc < 4; cc++) d[r][cc] = base[(r * 10 + cc) * 33];
            float tm[4][4];
            for (int j = 0; j < 4; j++) {
                tm[0][j] = d[0][j] - d[2][j];
                tm[1][j] = d[1][j] + d[2][j];
                tm[2][j] = d[2][j] - d[1][j];
                tm[3][j] = d[1][j] - d[3][j];
            }
            for (int i = 0; i < 4; i++) {
                Vs[(i * 4 + 0) * 512 + ci * 16 + tl] = tm[i][0] - tm[i][2];
                Vs[(i * 4 + 1) * 512 + ci * 16 + tl] = tm[i][1] + tm[i][2];
                Vs[(i * 4 + 2) * 512 + ci * 16 + tl] = tm[i][2] - tm[i][1];
                Vs[(i * 4 + 3) * 512 + ci * 16 + tl] = tm[i][1] - tm[i][3];
            }
        }
        __syncthreads();

        {
            int uv = g16;
            int q = c >> 3;
            int j = c & 7;
            float acc[16];
            for (int i = 0; i < 16; i++) acc[i] = 0.f;
            const float4* V4 = (const float4*)(Vs + uv * 512) + q;
            const float4* U4 = (const float4*)(g_U + (L * 16 + uv) * 1024) + j;
            #pragma unroll 8
            for (int ci = 0; ci < 32; ci++) {
                float4 v = V4[ci * 4];
                float4 u = U4[ci * 8];
                acc[0]  = fmaf(v.x, u.x, acc[0]);
                acc[1]  = fmaf(v.x, u.y, acc[1]);
                acc[2]  = fmaf(v.x, u.z, acc[2]);
                acc[3]  = fmaf(v.x, u.w, acc[3]);
                acc[4]  = fmaf(v.y, u.x, acc[4]);
                acc[5]  = fmaf(v.y, u.y, acc[5]);
                acc[6]  = fmaf(v.y, u.z, acc[6]);
                acc[7]  = fmaf(v.y, u.w, acc[7]);
                acc[8]  = fmaf(v.z, u.x, acc[8]);
                acc[9]  = fmaf(v.z, u.y, acc[9]);
                acc[10] = fmaf(v.z, u.z, acc[10]);
                acc[11] = fmaf(v.z, u.w, acc[11]);
                acc[12] = fmaf(v.w, u.x, acc[12]);
                acc[13] = fmaf(v.w, u.y, acc[13]);
                acc[14] = fmaf(v.w, u.z, acc[14]);
                acc[15] = fmaf(v.w, u.w, acc[15]);
            }
            float* Mw = Ms + uv * 544 + (q * 4) * 34 + j;
            for (int tlk = 0; tlk < 4; tlk++)
                for (int k = 0; k < 4; k++)
                    Mw[tlk * 34 + k * 8] = acc[tlk * 4 + k];
        }
        __syncthreads();

        {
            int co2 = t & 31; int tl = t >> 5;
            int ty = tl >> 2; int tx = tl & 3;
            float M[4][4];
            for (int i = 0; i < 4; i++) for (int j = 0; j < 4; j++) M[i][j] = Ms[(i * 4 + j) * 544 + tl * 34 + co2];
            float t0[2][4];
            for (int j = 0; j < 4; j++) {
                t0[0][j] = M[0][j] + M[1][j] + M[2][j];
                t0[1][j] = M[1][j] - M[2][j] - M[3][j];
            }
            float a = Asc[co2], bo = Bof[co2];
            for (int i = 0; i < 2; i++) {
                float y0 = t0[i][0] + t0[i][1] + t0[i][2];
                float y1 = t0[i][1] - t0[i][2] - t0[i][3];
                int rr = 1 + 2 * ty + i;
                int cc0 = 1 + 2 * tx;
                outb[(rr * 10 + cc0) * 33 + co2] = gelu_f(y0 * a + bo);
                outb[(rr * 10 + cc0 + 1) * 33 + co2] = gelu_f(y1 * a + bo);
            }
        }
        __syncthreads();
    }

    {
        int y = g16 >> 1;
        int x0 = (g16 & 1) * 4;
        float acc[4];
        for (int x = 0; x < 4; x++) acc[x] = 0.f;
        for (int dy = 0; dy < 3; dy++) for (int dx = 0; dx < 3; dx++) {
            float wv = w4s[c * 9 + dy * 3 + dx];
            const float* rp = bufA + ((y + dy) * 10 + x0 + dx) * 33 + c;
            for (int x = 0; x < 4; x++) acc[x] = fmaf(wv, rp[x * 33], acc[x]);
        }
        for (int x = 0; x < 4; x++) {
            float v = acc[x];
            for (int o = 16; o; o >>= 1) v += __shfl_xor_sync(0xffffffffu, v, o);
            if (c == 0) flat[y * 8 + x0 + x] = gelu_f(v * AB4[0] + AB4[1]);
        }
    }
    __syncthreads();

    {
        int e = t & 63;
        int h = t >> 6;
        int j0 = h * 8;
        float p = 0.f;
        for (int jj = 0; jj < 8; jj += 4) {
            float4 lw = *(const float4*)(lin_w + e * 64 + j0 + jj);
            p = fmaf(lw.x, flat[j0 + jj], p);
            p = fmaf(lw.y, flat[j0 + jj + 1], p);
            p = fmaf(lw.z, flat[j0 + jj + 2], p);
            p = fmaf(lw.w, flat[j0 + jj + 3], p);
        }
        red[h * 64 + e] = p;
        __syncthreads();
        if (t < 64) {
            float s = 0.f;
            for (int h2 = 0; h2 < 8; h2++) s += red[h2 * 64 + t];
            g_feats[img * 64 + t] = s;
        }
    }
}

// ======== LoR adapter: 16 tok/block, token-blocked GEMVs (weight bytes /4) ========
__global__ __launch_bounds__(1024) void lor_kernel(
    const float* __restrict__ emb, const float* __restrict__ w1, const float* __restrict__ w2,
    const float* __restrict__ tags, const float* __restrict__ rq, const float* __restrict__ rk,
    const float* __restrict__ rv, const float* __restrict__ ro,
    const float* __restrict__ lnw, const float* __restrict__ lnb, const int* __restrict__ sys)
{
    extern __shared__ float sm[];
    float* w1S = sm;             // 4352 [e*68+d]
    float* w2S = sm + 4352;      // 4352
    float* rqS = sm + 8704;      // 4352
    float* roS = sm + 13056;     // 4160 [d*65+j] natural
    float* rkT = sm + 17216;     // 1024
    float* rvS = sm + 18240;     // 1024
    float* part4 = sm + 19264;   // 4096 [p*1024 + lt*64 + j]
    float* ahs = sm + 23360;     // 1024
    float* qvs = sm + 24384;     // 1024
    float* lvs = sm + 25408;     // 1024
    float* rA = sm + 26432;      // 32
    float* rB = sm + 26464;      // 32
    float* bndS = sm + 26496;    // 256
    float* tgS = sm + 26752;     // 256
    float* tgwS = sm + 27008;    // 256 -> total 27264 floats = 109056 B
    const int t = threadIdx.x;

    for (int i = t; i < 4096; i += 1024) {
        int a = i >> 6; int bq = i & 63;
        w1S[a * 68 + bq] = w1[i];
        w2S[a * 68 + bq] = w2[i];
        rqS[a * 68 + bq] = rq[i];
        roS[a * 65 + bq] = ro[i];
    }
    {
        int n = t >> 8; int h = (t >> 4) & 15; int r = t & 15;
        rkT[t] = rk[(r * 4 + n) * 16 + h];
        rvS[t] = rv[t];
    }
    if (t < 256) {
        tgS[t] = tags[t];
        tgwS[t] = g_tagw[t];
    }

    const int lt = t >> 6;
    const int j = t & 63;
    const int tok = blockIdx.x * 16 + lt;
    const int b = tok / 24;
    const int k24 = tok - b * 24;
    const int s = k24 >> 2;
    const int tg = k24 & 3;
    const int g4 = lt >> 2;
    // token-blocked mapping
    const int jb = t & 63;
    const int pq = (t >> 6) & 3;
    const int gg = t >> 8;
    if ((lt & 3) == 0) {
        int cls = sys[b * 6 + s];
        bndS[g4 * 64 + j] = g_feats[(b * 6 + s) * 64 + j] + emb[cls * 64 + j];
    }
    __syncthreads();
    // h1 GEMV (bound shared by group): thread (lt=g4*4+p, j), d in [p*16,p*16+16)
    {
        int p = lt & 3;
        float hp = 0.f;
        const float4* wr = (const float4*)(w1S + j * 68) + p * 4;
        const float4* ar = (const float4*)(bndS + g4 * 64) + p * 4;
        #pragma unroll
        for (int k = 0; k < 4; k++) {
            float4 w = wr[k];
            float4 a = ar[k];
            hp = fmaf(w.x, a.x, hp);
            hp = fmaf(w.y, a.y, hp);
            hp = fmaf(w.z, a.z, hp);
            hp = fmaf(w.w, a.w, hp);
        }
        part4[t] = hp;
    }
    __syncthreads();
    {
        float h1 = part4[(g4 * 4 + 0) * 64 + j] + part4[(g4 * 4 + 1) * 64 + j]
                 + part4[(g4 * 4 + 2) * 64 + j] + part4[(g4 * 4 + 3) * 64 + j]
                 + tgwS[tg * 64 + j];
        ahs[t] = gelu_f(h1);
    }
    __syncthreads();
    // qv GEMV token-blocked: thread (gg,pq,jb) -> 4 tokens, weight loaded once
    {
        const float4* wr = (const float4*)(w2S + jb * 68) + pq * 4;
        float4 w0 = wr[0], w1v = wr[1], w2v = wr[2], w3v = wr[3];
        #pragma unroll
        for (int k = 0; k < 4; k++) {
            const float4* ar = (const float4*)(ahs + (gg * 4 + k) * 64) + pq * 4;
            float4 a0 = ar[0], a1 = ar[1], a2 = ar[2], a3 = ar[3];
            float sp = 0.f;
            sp = fmaf(w0.x, a0.x, sp); sp = fmaf(w0.y, a0.y, sp);
            sp = fmaf(w0.z, a0.z, sp); sp = fmaf(w0.w, a0.w, sp);
            sp = fmaf(w1v.x, a1.x, sp); sp = fmaf(w1v.y, a1.y, sp);
            sp = fmaf(w1v.z, a1.z, sp); sp = fmaf(w1v.w, a1.w, sp);
            sp = fmaf(w2v.x, a2.x, sp); sp = fmaf(w2v.y, a2.y, sp);
            sp = fmaf(w2v.z, a2.z, sp); sp = fmaf(w2v.w, a2.w, sp);
            sp = fmaf(w3v.x, a3.x, sp); sp = fmaf(w3v.y, a3.y, sp);
            sp = fmaf(w3v.z, a3.z, sp); sp = fmaf(w3v.w, a3.w, sp);
            part4[pq * 1024 + (gg * 4 + k) * 64 + jb] = sp;
        }
    }
    __syncthreads();
    qvs[t] = part4[lt * 64 + j] + part4[1024 + lt * 64 + j]
           + part4[2048 + lt * 64 + j] + part4[3072 + lt * 64 + j];
    __syncthreads();
    // qh GEMV token-blocked (rq)
    {
        const float4* wr = (const float4*)(rqS + jb * 68) + pq * 4;
        float4 w0 = wr[0], w1v = wr[1], w2v = wr[2], w3v = wr[3];
        #pragma unroll
        for (int k = 0; k < 4; k++) {
            const float4* ar = (const float4*)(qvs + (gg * 4 + k) * 64) + pq * 4;
            float4 a0 = ar[0], a1 = ar[1], a2 = ar[2], a3 = ar[3];
            float sp = 0.f;
            sp = fmaf(w0.x, a0.x, sp); sp = fmaf(w0.y, a0.y, sp);
            sp = fmaf(w0.z, a0.z, sp); sp = fmaf(w0.w, a0.w, sp);
            sp = fmaf(w1v.x, a1.x, sp); sp = fmaf(w1v.y, a1.y, sp);
            sp = fmaf(w1v.z, a1.z, sp); sp = fmaf(w1v.w, a1.w, sp);
            sp = fmaf(w2v.x, a2.x, sp); sp = fmaf(w2v.y, a2.y, sp);
            sp = fmaf(w2v.z, a2.z, sp); sp = fmaf(w2v.w, a2.w, sp);
            sp = fmaf(w3v.x, a3.x, sp); sp = fmaf(w3v.y, a3.y, sp);
            sp = fmaf(w3v.z, a3.z, sp); sp = fmaf(w3v.w, a3.w, sp);
            part4[pq * 1024 + (gg * 4 + k) * 64 + jb] = sp;
        }
    }
    __syncthreads();
    float qh = part4[lt * 64 + j] + part4[1024 + lt * 64 + j]
             + part4[2048 + lt * 64 + j] + part4[3072 + lt * 64 + j];
    const int n = j >> 4;
    const int sub = j & 15;
    float scv = 0.f;
    for (int hh = 0; hh < 16; hh++) {
        float q2 = __shfl_sync(0xffffffffu, qh, hh, 16);
        scv = fmaf(q2, rkT[(n * 16 + hh) * 16 + sub], scv);
    }
    scv *= 0.25f;
    float mx = scv;
    for (int o = 8; o; o >>= 1) mx = fmaxf(mx, __shfl_xor_sync(0xffffffffu, mx, o, 16));
    float ee = expf(scv - mx);
    float ss = ee;
    for (int o = 8; o; o >>= 1) ss += __shfl_xor_sync(0xffffffffu, ss, o, 16);
    float p = ee / ss;
    float lv = 0.f;
    for (int r = 0; r < 16; r++) {
        float pr = __shfl_sync(0xffffffffu, p, r, 16);
        lv = fmaf(pr, rvS[(r * 4 + n) * 16 + sub], lv);
    }
    lvs[t] = lv;
    __syncthreads();
    // ov GEMV token-blocked, ro natural [d][j] (scalar, conflict-free)
    {
        float wreg[16];
        #pragma unroll
        for (int dd = 0; dd < 16; dd++) wreg[dd] = roS[(pq * 16 + dd) * 65 + jb];
        #pragma unroll
        for (int k = 0; k < 4; k++) {
            const float* ar = lvs + (gg * 4 + k) * 64 + pq * 16;
            float sp = 0.f;
            #pragma unroll
            for (int dd = 0; dd < 16; dd++) sp = fmaf(wreg[dd], ar[dd], sp);
            part4[pq * 1024 + (gg * 4 + k) * 64 + jb] = sp;
        }
    }
    __syncthreads();
    float ov = part4[lt * 64 + j] + part4[1024 + lt * 64 + j]
             + part4[2048 + lt * 64 + j] + part4[3072 + lt * 64 + j];
    float z = ov + bndS[g4 * 64 + j] + tgS[tg * 64 + j];
    float sv = z;
    for (int o = 16; o; o >>= 1) sv += __shfl_xor_sync(0xffffffffu, sv, o);
    int wh = j >> 5;
    if ((j & 31) == 0) rA[lt * 2 + wh] = sv;
    __syncthreads();
    float mean = (rA[lt * 2] + rA[lt * 2 + 1]) * 0.015625f;
    float dz = z - mean;
    float v2 = dz * dz;
    for (int o = 16; o; o >>= 1) v2 += __shfl_xor_sync(0xffffffffu, v2, o);
    if ((j & 31) == 0) rB[lt * 2 + wh] = v2;
    __syncthreads();
    float var = (rB[lt * 2] + rB[lt * 2 + 1]) * 0.015625f;
    g_lors[tok * 64 + j] = dz * rsqrtf(var + 1e-5f) * lnw[j] + lnb[j];
}

// ============ query path: 4 tasks/block, 256 threads, grid 128 ============
__global__ __launch_bounds__(256) void query_kernel(
    const float* __restrict__ emb, const float* __restrict__ w1, const float* __restrict__ w2,
    const float* __restrict__ tags, const int* __restrict__ qys)
{
    extern __shared__ float sm[];
    float* w1T = sm;
    float* w2T = sm + 4160;
    float* lorS = sm + 8320;
    float* xq = sm + 14464;
    float* ah = sm + 14976;
    float* pd = sm + 15488;
    float* d1 = sm + 16000;
    float* d2 = sm + 16048;
    float* lg = sm + 16096;
    float* ls = sm + 16112;
    float* cr = sm + 16120;
    const int t = threadIdx.x;
    for (int i = t; i < 4096; i += 256) {
        int e = i >> 6; int d = i & 63;
        w1T[d * 65 + e] = w1[i];
        w2T[d * 65 + e] = w2[i];
    }
    for (int i = t; i < 6144; i += 256) lorS[i] = g_lors[blockIdx.x * 6144 + i];
    const int bl = t >> 6;
    const int e = t & 63;
    const int b = blockIdx.x * 4 + bl;
    for (int q = 0; q < 2; q++) xq[(bl * 2 + q) * 64 + e] = g_feats[3072 * 64 + (b * 2 + q) * 64 + e] + tags[4 * 64 + e];
    __syncthreads();
    if (e < 12) {
        int s = e >> 1; int q = e & 1;
        const float* r1 = lorS + bl * 1536 + (s * 4 + 1) * 64;
        const float* xx = xq + (bl * 2 + q) * 64;
        float a = 0.f;
        for (int d = 0; d < 64; d++) a = fmaf(r1[d], xx[d], a);
        d1[bl * 12 + e] = a;
    }
    __syncthreads();
    for (int q = 0; q < 2; q++) {
        const float* xx = xq + (bl * 2 + q) * 64;
        float a = 0.f;
        for (int d = 0; d < 64; d++) a = fmaf(w1T[d * 65 + e], xx[d], a);
        for (int s = 0; s < 6; s++) a = fmaf(lorS[bl * 1536 + (s * 4) * 64 + e], d1[bl * 12 + s * 2 + q], a);
        ah[(bl * 2 + q) * 64 + e] = gelu_f(a);
    }
    __syncthreads();
    if (e < 12) {
        int s = e >> 1; int q = e & 1;
        const float* r2 = lorS + bl * 1536 + (s * 4 + 3) * 64;
        const float* aa = ah + (bl * 2 + q) * 64;
        float a = 0.f;
        for (int d = 0; d < 64; d++) a = fmaf(r2[d], aa[d], a);
        d2[bl * 12 + e] = a;
    }
    __syncthreads();
    for (int q = 0; q < 2; q++) {
        const float* aa = ah + (bl * 2 + q) * 64;
        float a = 0.f;
        for (int d = 0; d < 64; d++) a = fmaf(w2T[d * 65 + e], aa[d], a);
        for (int s = 0; s < 6; s++) a = fmaf(lorS[bl * 1536 + (s * 4 + 2) * 64 + e], d2[bl * 12 + s * 2 + q], a);
        pd[(bl * 2 + q) * 64 + e] = a;
    }
    __syncthreads();
    if (e < 4) {
        int q = e >> 1; int l = e & 1;
        float a = 0.f;
        for (int d = 0; d < 64; d++) a = fmaf(emb[l * 64 + d], pd[(bl * 2 + q) * 64 + d], a);
        lg[bl * 4 + e] = a;
    }
    __syncthreads();
    if (e < 2) {
        float l0 = lg[bl * 4 + e * 2];
        float l1 = lg[bl * 4 + e * 2 + 1];
        int yv = qys[b * 2 + e];
        float m = fmaxf(l0, l1);
        float lse = m + logf(expf(l0 - m) + expf(l1 - m));
        ls[bl * 2 + e] = lse - (yv ? l1 : l0);
        cr[bl * 2 + e] = (((l1 > l0) ? 1 : 0) == yv) ? 1.f : 0.f;
    }
    __syncthreads();
    if (t == 0) {
        float sl = 0.f;
        float sc = 0.f;
        for (int i = 0; i < 8; i++) { sl += ls[i]; sc += cr[i]; }
        g_ploss[blockIdx.x] = sl;
        g_pcorr[blockIdx.x] = sc;
    }
}

__global__ void reduce_kernel(float* __restrict__ out)
{
    __shared__ float sl[128];
    __shared__ float sc[128];
    int t = threadIdx.x;
    sl[t] = g_ploss[t];
    sc[t] = g_pcorr[t];
    __syncthreads();
    for (int s = 64; s; s >>= 1) {
        if (t < s) { sl[t] += sl[t + s]; sc[t] += sc[t + s]; }
        __syncthreads();
    }
    if (t == 0) {
        float loss = sl[0] * 0.0009765625f;
        out[0] = loss;
        out[1] = loss;
        out[2] = 0.f;
        out[3] = sc[0];
        out[4] = 1024.f;
    }
}

extern "C" void kernel_launch(void* const* d_in, const int* in_sizes, int n_in,
                              void* d_out, int out_size)
{
    const float* sxs = (const float*)d_in[1];
    const float* qxs = (const float*)d_in[2];
    const float* c1w = (const float*)d_in[4];
    const float* c1b = (const float*)d_in[5];
    const float* bn1 = (const float*)d_in[6];
    const float* c2w = (const float*)d_in[7];
    const float* c2b = (const float*)d_in[8];
    const float* bn2 = (const float*)d_in[9];
    const float* c3w = (const float*)d_in[10];
    const float* c3b = (const float*)d_in[11];
    const float* bn3 = (const float*)d_in[12];
    const float* c4w = (const float*)d_in[13];
    const float* c4b = (const float*)d_in[14];
    const float* bn4 = (const float*)d_in[15];
    const float* lin_w = (const float*)d_in[16];
    const float* emb = (const float*)d_in[17];
    const float* w1 = (const float*)d_in[18];
    const float* w2 = (const float*)d_in[19];
    const float* tags = (const float*)d_in[20];
    const float* rq = (const float*)d_in[21];
    const float* rk = (const float*)d_in[22];
    const float* rv = (const float*)d_in[23];
    const float* ro = (const float*)d_in[24];
    const float* lnw = (const float*)d_in[25];
    const float* lnb = (const float*)d_in[26];
    const int* sys = (const int*)d_in[27];
    const int* qys = (const int*)d_in[28];
    const size_t smF = 24848 * sizeof(float);
    const size_t smL = 27264 * sizeof(float);
    const size_t smQ = 16128 * sizeof(float);
    cudaFuncSetAttribute(feat_kernel, cudaFuncAttributeMaxDynamicSharedMemorySize, (int)smF);
    cudaFuncSetAttribute(lor_kernel, cudaFuncAttributeMaxDynamicSharedMemorySize, (int)smL);
    cudaFuncSetAttribute(query_kernel, cudaFuncAttributeMaxDynamicSharedMemorySize, (int)smQ);
    // lor_kernel sits at 0-based position 3 (ncu capture slot)
    wtrans_kernel<<<2, 256>>>(c2w, c3w);
    prep_kernel<<<1, 256>>>(w1, tags);
    feat_kernel<<<4096, 512, smF>>>(sxs, qxs, c1w, c1b, bn1, c2b, bn2, c3b, bn3, c4w, c4b, bn4, lin_w);
    lor_kernel<<<768, 1024, smL>>>(emb, w1, w2, tags, rq, rk, rv, ro, lnw, lnb, sys);
    query_kernel<<<128, 256, smQ>>>(emb, w1, w2, tags, qys);
    reduce_kernel<<<1, 128>>>((float*)d_out);
}